// round 14
// baseline (speedup 1.0000x reference)
#include <cuda_runtime.h>
#include <cstdint>

#define B_ 8
#define N_ 40000
#define C_ 80
#define TOPK_ 500
#define M_ (B_ * TOPK_)   // 4000
#define NANCH (B_ * N_)   // 320000
#define NBINS 4096
#define CANDCAP 2048
#define NQ4 (N_ / 4)      // 10000 float4 per batch
#define KEPT_CAP 80       // smem kept-boxes per NMS group (global spill beyond)

// Fixed collect threshold: count(score >= T0) ~ 744 +/- 27 per batch for
// sigmoid(max of 80 N(0,1)) scores; exact histogram fallback covers any
// distribution where nsel falls outside [500, 1024].
#define T0_SCORE 0.9707f

// ---------------- scratch (device globals; no allocations) ----------------
__device__ float g_scores[NANCH];
__device__ int   g_labels[NANCH];
__device__ unsigned g_maxbits;           // monotone-uint max of gathered coords
__device__ float4 g_kept[640 * 512];     // NMS kept-list spill (rarely touched)
__device__ unsigned g_done;              // topk blocks completed (reset each run)
__device__ unsigned g_reset;             // nms blocks completed  (reset each run)

__device__ __forceinline__ int score_bin(unsigned k) {
    int bin = ((int)(k >> 11)) - (0x3F000000 >> 11);
    return max(0, min(NBINS - 1, bin));
}

// ---------------- XLA-exact sigmoid: 0.5 + 0.5*fast_tanh(0.5x) ------------
__device__ __forceinline__ float jax_sigmoid(float x) {
    float t  = __fmul_rn(0.5f, x);                 // exact
    float at = fabsf(t);
    float tc = fminf(fmaxf(t, -7.99881172180175781f), 7.99881172180175781f);
    float x2 = __fmul_rn(tc, tc);
    float p = -2.76076847742355e-16f;
    p = fmaf(x2, p,  2.00018790482477e-13f);
    p = fmaf(x2, p, -8.60467152213735e-11f);
    p = fmaf(x2, p,  5.12229709037114e-08f);
    p = fmaf(x2, p,  1.48572235717979e-05f);
    p = fmaf(x2, p,  6.37261928875436e-04f);
    p = fmaf(x2, p,  4.89352455891786e-03f);
    p = __fmul_rn(tc, p);
    float q = 1.19825839466702e-06f;
    q = fmaf(x2, q, 1.18534705686654e-04f);
    q = fmaf(x2, q, 2.26843463243900e-03f);
    q = fmaf(x2, q, 4.89352518554385e-03f);
    float r  = __fdiv_rn(p, q);
    float th = (at < 0.0004f) ? t : r;
    return __fadd_rn(0.5f, __fmul_rn(0.5f, th));   // 0.5*th exact -> unambiguous
}

__device__ __forceinline__ unsigned mono_bits(float f) {
    int iv = __float_as_int(f);
    return (iv >= 0) ? ((unsigned)iv | 0x80000000u) : (unsigned)(~iv);
}

// ---------------- K1: per-anchor max/argmax, 4 lanes per anchor ------------
// Each lane owns 20 classes (5 contiguous float4 loaded up front for MLP).
// Streaming top-2 + shfl merge; exact sigmoid re-scan fallback when top-2
// gap < 1e-3 (sigmoid could tie after rounding). min-blocks=6 caps regs at
// 40 (proven no-spill; occupancy beyond this is not binding).
__global__ void __launch_bounds__(256, 6) k1_scores(const float* __restrict__ pconf) {
    if (blockIdx.x == 0 && threadIdx.x == 0) g_maxbits = 0u;   // reset for k23
    int gt = blockIdx.x * 256 + threadIdx.x;
    int a = gt >> 2;
    if (a >= NANCH) return;
    const int sub  = gt & 3;
    const int lane = threadIdx.x & 31;
    const unsigned gm = 0xFu << (lane & ~3);       // 4-lane group mask

    const float4* p = reinterpret_cast<const float4*>(pconf + (size_t)a * C_) + sub * 5;
    float4 v[5];
#pragma unroll
    for (int j = 0; j < 5; j++) v[j] = p[j];

    const int base = sub * 20;
    float m1 = -1e30f, m2 = -1e30f;
    int idx1 = 0;
#pragma unroll
    for (int j = 0; j < 5; j++) {
        float vals[4] = {v[j].x, v[j].y, v[j].z, v[j].w};
#pragma unroll
        for (int q = 0; q < 4; q++) {
            float val = vals[q];
            if (val > m1) { m2 = m1; m1 = val; idx1 = base + j * 4 + q; }
            else          { m2 = fmaxf(m2, val); }
        }
    }
    // merge top-2 across the 4 lanes (exact ties force m2==m1 -> fallback)
#pragma unroll
    for (int d = 1; d < 4; d <<= 1) {
        float om1 = __shfl_xor_sync(gm, m1, d);
        float om2 = __shfl_xor_sync(gm, m2, d);
        int   oi  = __shfl_xor_sync(gm, idx1, d);
        if (om1 > m1 || (om1 == m1 && oi < idx1)) {
            m2 = fmaxf(m1, om2); m1 = om1; idx1 = oi;
        } else {
            m2 = fmaxf(om1, m2);
        }
    }

    float bs; int bl;
    if (m1 - m2 >= 1e-3f) {
        bs = jax_sigmoid(m1);
        bl = idx1;
    } else {
        // exact path (group-uniform branch): reload row (L1-hot) and rescan
        float thr = m1 - 1e-3f;
        bs = -1.0f; bl = 0x7FFFFFFF;
#pragma unroll
        for (int j = 0; j < 5; j++) {
            float4 w = p[j];
            float vals[4] = {w.x, w.y, w.z, w.w};
#pragma unroll
            for (int q = 0; q < 4; q++) {
                if (vals[q] > thr) {
                    float s = jax_sigmoid(vals[q]);
                    if (s > bs) { bs = s; bl = base + j * 4 + q; }  // first idx in-lane
                }
            }
        }
#pragma unroll
        for (int d = 1; d < 4; d <<= 1) {
            float obs = __shfl_xor_sync(gm, bs, d);
            int   obl = __shfl_xor_sync(gm, bl, d);
            if (obs > bs || (obs == bs && obl < bl)) { bs = obs; bl = obl; }
        }
    }
    if (sub == 0) {
        g_scores[a] = bs;
        g_labels[a] = bl;
    }
}

// ---------------- K23: fused top-500 + grouped greedy NMS ------------------
// 28 co-resident blocks (< 148 SMs -> all start immediately, no deadlock):
//   blocks 0..7  : per-batch exact top-500 (jax.lax.top_k stable order),
//                  fixed-threshold collect + hybrid bitonic; histogram
//                  fallback for adversarial distributions.
//   blocks 8..27 : 32 NMS warps each = 640 (label,batch) groups. They spin
//                  on g_done (one poller thread/block) until all 8 topk
//                  blocks have published, then run warp-parallel greedy NMS.
// Cross-group IoU is exactly 0 (offset spacing >= 2.1 > box extent), so
// per-group greedy in rank order == jax's global greedy.
__global__ void __launch_bounds__(1024, 1) k23_fused(const float* __restrict__ pboxes,
                                                     float* __restrict__ out) {
    // 40KB smem union: topk arrays vs NMS kept-lists (block runs ONE role)
    __shared__ __align__(16) unsigned char smem_raw[40960];
    __shared__ int s_pivot, s_nsel, s_tstar, s_go;
    __shared__ unsigned s_maxb;

    const int tid = threadIdx.x;

    if (blockIdx.x < B_) {
        // ===================== TOPK role =====================
        unsigned*           hist = (unsigned*)smem_raw;                    // 16KB
        unsigned long long* cand = (unsigned long long*)(smem_raw + 16384);// 16KB
        unsigned*           sA   = (unsigned*)(smem_raw + 32768);          // 4KB
        unsigned*           sB   = (unsigned*)(smem_raw + 36864);          // 4KB

        const int b = blockIdx.x;
        const float4* sc4 = reinterpret_cast<const float4*>(g_scores + b * N_);

        if (tid == 0) { s_maxb = 0u; s_nsel = 0; }
        cand[tid] = ~0ULL;                // fast path sorts only 1024 slots
        __syncthreads();

        // fast collect: fixed threshold (scores are L2-hot, written by k1)
#pragma unroll
        for (int j = 0; j < 10; j++) {
            int i4 = j * 1024 + tid;
            if (i4 < NQ4) {
                float4 v = sc4[i4];
                float vals[4] = {v.x, v.y, v.z, v.w};
#pragma unroll
                for (int q = 0; q < 4; q++) {
                    if (vals[q] >= T0_SCORE) {
                        unsigned k = __float_as_uint(vals[q]);
                        int pos = atomicAdd(&s_nsel, 1);
                        if (pos < CANDCAP)
                            cand[pos] = ((unsigned long long)(~k) << 32)
                                      | (unsigned)(i4 * 4 + q);
                    }
                }
            }
        }
        __syncthreads();

        int nsel = s_nsel;
        int SZ = 1024;
        if (nsel < TOPK_ || nsel > 1024) {
            // ---------- exact fallback: histogram pivot + recollect ----------
            for (int i = tid; i < NBINS; i += 1024) hist[i] = 0u;
            for (int i = tid; i < CANDCAP; i += 1024) cand[i] = ~0ULL;
            if (tid == 0) s_nsel = 0;
            __syncthreads();
#pragma unroll
            for (int j = 0; j < 10; j++) {
                int i4 = j * 1024 + tid;
                if (i4 < NQ4) {
                    float4 v = sc4[i4];
                    float vals[4] = {v.x, v.y, v.z, v.w};
#pragma unroll
                    for (int q = 0; q < 4; q++)
                        atomicAdd(&hist[score_bin(__float_as_uint(vals[q]))], 1u);
                }
            }
            __syncthreads();
            unsigned s = hist[tid * 4] + hist[tid * 4 + 1] + hist[tid * 4 + 2] + hist[tid * 4 + 3];
            sA[tid] = s;
            __syncthreads();
            unsigned* src = sA; unsigned* dst = sB;
            for (int d = 1; d < 1024; d <<= 1) {
                unsigned vv = src[tid] + ((tid + d < 1024) ? src[tid + d] : 0u);
                dst[tid] = vv;
                __syncthreads();
                unsigned* t2 = src; src = dst; dst = t2;
            }
            unsigned* S = src;
            if (S[tid] >= TOPK_ && (tid == 1023 || S[tid + 1] < TOPK_)) s_tstar = tid;
            __syncthreads();
            if (tid == 0) {
                int t = s_tstar;
                unsigned cum = (t == 1023) ? 0u : S[t + 1];
                int P = t * 4;
                for (int bin = t * 4 + 3; bin >= t * 4; bin--) {
                    cum += hist[bin];
                    if (cum >= TOPK_) { P = bin; break; }
                }
                s_pivot = P;
            }
            __syncthreads();
            const int P = s_pivot;
#pragma unroll
            for (int j = 0; j < 10; j++) {
                int i4 = j * 1024 + tid;
                if (i4 < NQ4) {
                    float4 v = sc4[i4];
                    float vals[4] = {v.x, v.y, v.z, v.w};
#pragma unroll
                    for (int q = 0; q < 4; q++) {
                        unsigned k = __float_as_uint(vals[q]);
                        if (score_bin(k) >= P) {
                            int pos = atomicAdd(&s_nsel, 1);
                            if (pos < CANDCAP)
                                cand[pos] = ((unsigned long long)(~k) << 32)
                                          | (unsigned)(i4 * 4 + q);
                        }
                    }
                }
            }
            __syncthreads();
            SZ = (s_nsel <= 1024) ? 1024 : CANDCAP;
        }

        // sort ascending: (~key, idx) => score desc, index asc (stable order)
        if (SZ == 1024) {
            unsigned long long val = cand[tid];
            __syncthreads();
#pragma unroll
            for (int kk = 2; kk <= 1024; kk <<= 1) {
                for (int j = kk >> 1; j > 0; j >>= 1) {
                    unsigned long long o;
                    if (j >= 32) {
                        cand[tid] = val;
                        __syncthreads();
                        o = cand[tid ^ j];
                        __syncthreads();
                    } else {
                        o = __shfl_xor_sync(0xFFFFFFFFu, val, j);
                    }
                    bool up = ((tid & kk) == 0);
                    bool keepmin = (((tid & j) == 0) == up);
                    val = (keepmin == (val < o)) ? val : o;
                }
            }
            cand[tid] = val;
            __syncthreads();
        } else {
            for (int kk = 2; kk <= CANDCAP; kk <<= 1) {
                for (int j = kk >> 1; j > 0; j >>= 1) {
                    for (int i = tid; i < CANDCAP; i += 1024) {
                        int l = i ^ j;
                        if (l > i) {
                            unsigned long long a = cand[i], c = cand[l];
                            bool up = ((i & kk) == 0);
                            if ((a > c) == up) { cand[i] = c; cand[l] = a; }
                        }
                    }
                    __syncthreads();
                }
            }
        }

        if (tid < TOPK_) {
            unsigned long long skv = cand[tid];
            unsigned idx = (unsigned)(skv & 0xFFFFFFFFu);
            unsigned kb  = ~((unsigned)(skv >> 32));
            float score  = __uint_as_float(kb);
            int m = b * TOPK_ + tid;
            out[m] = (float)b;                                      // ids_batch1
            float4 box = reinterpret_cast<const float4*>(pboxes)[b * N_ + idx];
            reinterpret_cast<float4*>(out + M_)[m] = box;           // p_boxes1
            out[5 * M_ + m] = (float)g_labels[b * N_ + idx];        // p_labels1
            out[6 * M_ + m] = score;                                // p_scores1
            unsigned lm = max(max(mono_bits(box.x), mono_bits(box.y)),
                              max(mono_bits(box.z), mono_bits(box.w)));
            atomicMax(&s_maxb, lm);
        }
        __syncthreads();
        if (tid == 0) atomicMax(&g_maxbits, s_maxb);
        __threadfence();                  // publish out + g_maxbits gpu-wide
        __syncthreads();
        if (tid == 0) atomicAdd(&g_done, 1u);
    } else {
        // ===================== NMS role =====================
        float4* kept_all = (float4*)smem_raw;         // 32 * KEPT_CAP * 16B = 40KB

        // wait until all 8 topk blocks have published
        if (tid == 0) {
            while (*((volatile unsigned*)&g_done) < (unsigned)B_) __nanosleep(64);
            s_go = 1;
        }
        __syncthreads();
        (void)s_go;
        __threadfence();                  // acquire side

        const int lane = tid & 31;
        const int wid  = tid >> 5;
        const int g    = (blockIdx.x - B_) * 32 + wid;   // 0..639
        const int bb   = g & 7;
        const float fc = (float)(g >> 3);
        const unsigned gm = 0xFFFFFFFFu;

        unsigned mb = g_maxbits;
        int ivb = (mb & 0x80000000u) ? (int)(mb & 0x7FFFFFFFu) : ~((int)mb);
        const float mc1 = __fadd_rn(__int_as_float(ivb), 1.0f);
        const float off = __fmul_rn((float)g, mc1);

        float4* kept = kept_all + wid * KEPT_CAP;
        float4* kspill = &g_kept[g * 512];
        int nk = 0;

        for (int it = 0; it < 16; it++) {
            int r = it * 32 + lane;
            int m = bb * TOPK_ + r;
            bool pred = false;
            if (r < TOPK_) {
                float lab = out[5 * M_ + m];
                float scv = out[6 * M_ + m];
                bool valid = scv > 0.05f;
                pred = valid && (lab == fc);
                if (!valid && fc == 0.0f) out[7 * M_ + m] = 0.0f;  // invalid: keep=0
            }
            unsigned ball = __ballot_sync(gm, pred);
            float4 ob;
            if (pred) {
                float4 bx = reinterpret_cast<float4*>(out + M_)[m];
                ob.x = __fadd_rn(bx.x, off); ob.y = __fadd_rn(bx.y, off);
                ob.z = __fadd_rn(bx.z, off); ob.w = __fadd_rn(bx.w, off);
            }
            while (ball) {
                int src = __ffs(ball) - 1; ball &= ball - 1;
                float4 cb;
                cb.x = __shfl_sync(gm, ob.x, src);
                cb.y = __shfl_sync(gm, ob.y, src);
                cb.z = __shfl_sync(gm, ob.z, src);
                cb.w = __shfl_sync(gm, ob.w, src);
                bool sup = false;
                for (int t = lane; t < nk; t += 32) {
                    float4 kb = (t < KEPT_CAP) ? kept[t] : kspill[t];
                    float ltx = fmaxf(kb.x, cb.x), lty = fmaxf(kb.y, cb.y);
                    float rbx = fminf(kb.z, cb.z), rby = fminf(kb.w, cb.w);
                    float wx = fmaxf(__fsub_rn(rbx, ltx), 0.0f);
                    float wy = fmaxf(__fsub_rn(rby, lty), 0.0f);
                    float inter = __fmul_rn(wx, wy);
                    float aa = __fmul_rn(__fsub_rn(kb.z, kb.x), __fsub_rn(kb.w, kb.y));
                    float ab = __fmul_rn(__fsub_rn(cb.z, cb.x), __fsub_rn(cb.w, cb.y));
                    float un = __fsub_rn(__fadd_rn(aa, ab), inter);
                    float iou = __fdiv_rn(inter, fmaxf(un, 1e-9f));
                    if (iou > 0.5f) sup = true;
                }
                unsigned sb = __ballot_sync(gm, sup);
                bool keepit = (sb == 0u);
                if (lane == src)
                    out[7 * M_ + bb * TOPK_ + it * 32 + src] = keepit ? 1.0f : 0.0f;
                if (keepit) {
                    if (lane == 0) {
                        if (nk < KEPT_CAP) kept[nk] = cb;
                        else               kspill[nk] = cb;
                    }
                    nk++;
                    if (nk > KEPT_CAP) __threadfence_block();  // spill visibility
                    __syncwarp(gm);
                }
            }
        }

        // last NMS block resets the flags for the next graph replay
        __syncthreads();
        if (tid == 0) {
            unsigned done = atomicAdd(&g_reset, 1u);
            if (done == 19u) {
                atomicExch(&g_done, 0u);
                atomicExch(&g_reset, 0u);
            }
        }
    }
}

// ---------------- host ----------------
extern "C" void kernel_launch(void* const* d_in, const int* in_sizes, int n_in,
                              void* d_out, int out_size) {
    const float* pconf  = (const float*)d_in[0];
    const float* pboxes = (const float*)d_in[1];
    float* out = (float*)d_out;
    (void)in_sizes; (void)n_in; (void)out_size;

    k1_scores<<<(NANCH * 4 + 255) / 256, 256>>>(pconf);
    k23_fused<<<28, 1024>>>(pboxes, out);
}

// round 15
// speedup vs baseline: 1.0950x; 1.0950x over previous
#include <cuda_runtime.h>
#include <cstdint>

#define B_ 8
#define N_ 40000
#define C_ 80
#define TOPK_ 500
#define M_ (B_ * TOPK_)   // 4000
#define NANCH (B_ * N_)   // 320000
#define NBINS 4096
#define CANDCAP 2048
#define NQ4 (N_ / 4)      // 10000 float4 per batch

// Fixed collect threshold: count(score >= T0) ~ 744 +/- 27 per batch for
// sigmoid(max of 80 N(0,1)) scores; exact histogram fallback covers any
// distribution where nsel falls outside [500, 1024].
#define T0_SCORE 0.9707f

// ---------------- scratch (device globals; no allocations) ----------------
__device__ float g_scores[NANCH];
__device__ int   g_labels[NANCH];
__device__ unsigned g_maxbits;           // monotone-uint max of gathered coords

__device__ __forceinline__ int score_bin(unsigned k) {
    int bin = ((int)(k >> 11)) - (0x3F000000 >> 11);
    return max(0, min(NBINS - 1, bin));
}

// ---------------- XLA-exact sigmoid: 0.5 + 0.5*fast_tanh(0.5x) ------------
__device__ __forceinline__ float jax_sigmoid(float x) {
    float t  = __fmul_rn(0.5f, x);                 // exact
    float at = fabsf(t);
    float tc = fminf(fmaxf(t, -7.99881172180175781f), 7.99881172180175781f);
    float x2 = __fmul_rn(tc, tc);
    float p = -2.76076847742355e-16f;
    p = fmaf(x2, p,  2.00018790482477e-13f);
    p = fmaf(x2, p, -8.60467152213735e-11f);
    p = fmaf(x2, p,  5.12229709037114e-08f);
    p = fmaf(x2, p,  1.48572235717979e-05f);
    p = fmaf(x2, p,  6.37261928875436e-04f);
    p = fmaf(x2, p,  4.89352455891786e-03f);
    p = __fmul_rn(tc, p);
    float q = 1.19825839466702e-06f;
    q = fmaf(x2, q, 1.18534705686654e-04f);
    q = fmaf(x2, q, 2.26843463243900e-03f);
    q = fmaf(x2, q, 4.89352518554385e-03f);
    float r  = __fdiv_rn(p, q);
    float th = (at < 0.0004f) ? t : r;
    return __fadd_rn(0.5f, __fmul_rn(0.5f, th));   // 0.5*th exact -> unambiguous
}

__device__ __forceinline__ unsigned mono_bits(float f) {
    int iv = __float_as_int(f);
    return (iv >= 0) ? ((unsigned)iv | 0x80000000u) : (unsigned)(~iv);
}

// ---------------- K1: per-anchor max/argmax, 4 lanes per anchor ------------
// Each lane owns 20 classes (5 contiguous float4 loaded up front for MLP).
// Streaming top-2 + shfl merge; exact sigmoid re-scan fallback when top-2
// gap < 1e-3 (sigmoid could tie after rounding). min-blocks=6 caps regs at
// 40 (proven no-spill; occupancy beyond this is not binding).
__global__ void __launch_bounds__(256, 6) k1_scores(const float* __restrict__ pconf) {
    if (blockIdx.x == 0 && threadIdx.x == 0) g_maxbits = 0u;   // reset for k2
    int gt = blockIdx.x * 256 + threadIdx.x;
    int a = gt >> 2;
    if (a >= NANCH) return;
    const int sub  = gt & 3;
    const int lane = threadIdx.x & 31;
    const unsigned gm = 0xFu << (lane & ~3);       // 4-lane group mask

    const float4* p = reinterpret_cast<const float4*>(pconf + (size_t)a * C_) + sub * 5;
    float4 v[5];
#pragma unroll
    for (int j = 0; j < 5; j++) v[j] = p[j];

    const int base = sub * 20;
    float m1 = -1e30f, m2 = -1e30f;
    int idx1 = 0;
#pragma unroll
    for (int j = 0; j < 5; j++) {
        float vals[4] = {v[j].x, v[j].y, v[j].z, v[j].w};
#pragma unroll
        for (int q = 0; q < 4; q++) {
            float val = vals[q];
            if (val > m1) { m2 = m1; m1 = val; idx1 = base + j * 4 + q; }
            else          { m2 = fmaxf(m2, val); }
        }
    }
    // merge top-2 across the 4 lanes (exact ties force m2==m1 -> fallback)
#pragma unroll
    for (int d = 1; d < 4; d <<= 1) {
        float om1 = __shfl_xor_sync(gm, m1, d);
        float om2 = __shfl_xor_sync(gm, m2, d);
        int   oi  = __shfl_xor_sync(gm, idx1, d);
        if (om1 > m1 || (om1 == m1 && oi < idx1)) {
            m2 = fmaxf(m1, om2); m1 = om1; idx1 = oi;
        } else {
            m2 = fmaxf(om1, m2);
        }
    }

    float bs; int bl;
    if (m1 - m2 >= 1e-3f) {
        bs = jax_sigmoid(m1);
        bl = idx1;
    } else {
        // exact path (group-uniform branch): reload row (L1-hot) and rescan
        float thr = m1 - 1e-3f;
        bs = -1.0f; bl = 0x7FFFFFFF;
#pragma unroll
        for (int j = 0; j < 5; j++) {
            float4 w = p[j];
            float vals[4] = {w.x, w.y, w.z, w.w};
#pragma unroll
            for (int q = 0; q < 4; q++) {
                if (vals[q] > thr) {
                    float s = jax_sigmoid(vals[q]);
                    if (s > bs) { bs = s; bl = base + j * 4 + q; }  // first idx in-lane
                }
            }
        }
#pragma unroll
        for (int d = 1; d < 4; d <<= 1) {
            float obs = __shfl_xor_sync(gm, bs, d);
            int   obl = __shfl_xor_sync(gm, bl, d);
            if (obs > bs || (obs == bs && obl < bl)) { bs = obs; bl = obl; }
        }
    }
    if (sub == 0) {
        g_scores[a] = bs;
        g_labels[a] = bl;
    }
}

// ---------------- K2: exact per-batch top-500 (jax.lax.top_k order) --------
// Fast path: fixed-threshold collect + BUCKET SORT on the score's high bits
// ((key-BASE)>>7 -> <=3840 buckets for ~744 candidates): 3-barrier warp
// scan of 4096 bins, scatter, per-bucket insertion sort (stable (~key,idx)
// order; erases scatter nondeterminism). Exact histogram-pivot fallback
// with full bitonic for adversarial distributions (cold).
__global__ void __launch_bounds__(1024) k2_topk(const float* __restrict__ pboxes,
                                                float* __restrict__ out) {
    // smem union: cand 16K | hist 16K | sorted 8K (fast) / sA+sB (fallback) | wsum
    __shared__ __align__(16) unsigned char sraw[16384 + 16384 + 8192 + 256];
    unsigned long long* cand   = (unsigned long long*)sraw;             // 2048
    unsigned*           hist   = (unsigned*)(sraw + 16384);             // 4096
    unsigned long long* sorted = (unsigned long long*)(sraw + 32768);   // 1024
    unsigned*           sA     = (unsigned*)(sraw + 32768);             // 1024 (fallback)
    unsigned*           sB     = (unsigned*)(sraw + 32768 + 4096);      // 1024 (fallback)
    unsigned*           wsum   = (unsigned*)(sraw + 32768 + 8192);      // 32
    __shared__ int s_pivot, s_nsel, s_tstar;
    __shared__ unsigned s_maxb;

    const int b = blockIdx.x;
    const int tid = threadIdx.x;
    const int lane = tid & 31;
    const int wid  = tid >> 5;
    const unsigned BASE = __float_as_uint(T0_SCORE);
    const float4* sc4 = reinterpret_cast<const float4*>(g_scores + b * N_);

    if (tid == 0) { s_maxb = 0u; s_nsel = 0; }
#pragma unroll
    for (int i = 0; i < 4; i++) hist[tid * 4 + i] = 0u;
    __syncthreads();

    // fast collect: fixed threshold; histogram built inline
#pragma unroll
    for (int j = 0; j < 10; j++) {
        int i4 = j * 1024 + tid;
        if (i4 < NQ4) {
            float4 v = sc4[i4];
            float vals[4] = {v.x, v.y, v.z, v.w};
#pragma unroll
            for (int q = 0; q < 4; q++) {
                if (vals[q] >= T0_SCORE) {
                    unsigned k = __float_as_uint(vals[q]);
                    unsigned rb = 4095u - min(4095u, (k - BASE) >> 7);
                    atomicAdd(&hist[rb], 1u);
                    int pos = atomicAdd(&s_nsel, 1);
                    if (pos < CANDCAP)
                        cand[pos] = ((unsigned long long)(~k) << 32)
                                  | (unsigned)(i4 * 4 + q);
                }
            }
        }
    }
    __syncthreads();

    const int nsel = s_nsel;
    const unsigned long long* res;

    if (nsel >= TOPK_ && nsel <= 1024) {
        // ============ fast path: bucket sort (7 barriers total) ============
        // exclusive scan of hist[0..4095] (ascending rbin = descending score)
        unsigned h0 = hist[tid * 4], h1 = hist[tid * 4 + 1];
        unsigned h2 = hist[tid * 4 + 2], h3 = hist[tid * 4 + 3];
        unsigned s = h0 + h1 + h2 + h3;
        unsigned inc = s;
#pragma unroll
        for (int d = 1; d < 32; d <<= 1) {
            unsigned n = __shfl_up_sync(0xFFFFFFFFu, inc, d);
            if (lane >= d) inc += n;
        }
        if (lane == 31) wsum[wid] = inc;
        __syncthreads();
        if (wid == 0) {
            unsigned v = wsum[lane];
            unsigned i2 = v;
#pragma unroll
            for (int d = 1; d < 32; d <<= 1) {
                unsigned n = __shfl_up_sync(0xFFFFFFFFu, i2, d);
                if (lane >= d) i2 += n;
            }
            wsum[lane] = i2 - v;          // exclusive warp offsets
        }
        __syncthreads();
        unsigned base0 = wsum[wid] + (inc - s);
        hist[tid * 4]     = base0;
        hist[tid * 4 + 1] = base0 + h0;
        hist[tid * 4 + 2] = base0 + h0 + h1;
        hist[tid * 4 + 3] = base0 + h0 + h1 + h2;
        __syncthreads();

        // scatter (hist: start -> end in place)
        if (tid < nsel) {
            unsigned long long v = cand[tid];
            unsigned k = ~((unsigned)(v >> 32));
            unsigned rb = 4095u - min(4095u, (k - BASE) >> 7);
            unsigned pos = atomicAdd(&hist[rb], 1u);
            sorted[pos] = v;
        }
        __syncthreads();

        // per-bucket stable insertion sort (full (~key,idx) compare)
        for (int r = tid; r < 4096; r += 1024) {
            int st = r ? (int)hist[r - 1] : 0;
            int en = (int)hist[r];
            for (int i2 = st + 1; i2 < en; i2++) {
                unsigned long long v = sorted[i2];
                int jx = i2;
                while (jx > st && sorted[jx - 1] > v) {
                    sorted[jx] = sorted[jx - 1]; jx--;
                }
                sorted[jx] = v;
            }
        }
        __syncthreads();
        res = sorted;
    } else {
        // ========== exact fallback: histogram pivot + bitonic sort ==========
        for (int i = tid; i < NBINS; i += 1024) hist[i] = 0u;
        for (int i = tid; i < CANDCAP; i += 1024) cand[i] = ~0ULL;
        if (tid == 0) s_nsel = 0;
        __syncthreads();
#pragma unroll
        for (int j = 0; j < 10; j++) {
            int i4 = j * 1024 + tid;
            if (i4 < NQ4) {
                float4 v = sc4[i4];
                float vals[4] = {v.x, v.y, v.z, v.w};
#pragma unroll
                for (int q = 0; q < 4; q++)
                    atomicAdd(&hist[score_bin(__float_as_uint(vals[q]))], 1u);
            }
        }
        __syncthreads();
        unsigned s = hist[tid * 4] + hist[tid * 4 + 1] + hist[tid * 4 + 2] + hist[tid * 4 + 3];
        sA[tid] = s;
        __syncthreads();
        unsigned* src = sA; unsigned* dst = sB;
        for (int d = 1; d < 1024; d <<= 1) {
            unsigned vv = src[tid] + ((tid + d < 1024) ? src[tid + d] : 0u);
            dst[tid] = vv;
            __syncthreads();
            unsigned* t2 = src; src = dst; dst = t2;
        }
        unsigned* S = src;
        if (S[tid] >= TOPK_ && (tid == 1023 || S[tid + 1] < TOPK_)) s_tstar = tid;
        __syncthreads();
        if (tid == 0) {
            int t = s_tstar;
            unsigned cum = (t == 1023) ? 0u : S[t + 1];
            int P = t * 4;
            for (int bin = t * 4 + 3; bin >= t * 4; bin--) {
                cum += hist[bin];
                if (cum >= TOPK_) { P = bin; break; }
            }
            s_pivot = P;
        }
        __syncthreads();
        const int P = s_pivot;
#pragma unroll
        for (int j = 0; j < 10; j++) {
            int i4 = j * 1024 + tid;
            if (i4 < NQ4) {
                float4 v = sc4[i4];
                float vals[4] = {v.x, v.y, v.z, v.w};
#pragma unroll
                for (int q = 0; q < 4; q++) {
                    unsigned k = __float_as_uint(vals[q]);
                    if (score_bin(k) >= P) {
                        int pos = atomicAdd(&s_nsel, 1);
                        if (pos < CANDCAP)
                            cand[pos] = ((unsigned long long)(~k) << 32)
                                      | (unsigned)(i4 * 4 + q);
                    }
                }
            }
        }
        __syncthreads();
        const int SZ = (s_nsel <= 1024) ? 1024 : CANDCAP;
        if (SZ == 1024) {
            unsigned long long val = cand[tid];
            __syncthreads();
#pragma unroll
            for (int kk = 2; kk <= 1024; kk <<= 1) {
                for (int j = kk >> 1; j > 0; j >>= 1) {
                    unsigned long long o;
                    if (j >= 32) {
                        cand[tid] = val;
                        __syncthreads();
                        o = cand[tid ^ j];
                        __syncthreads();
                    } else {
                        o = __shfl_xor_sync(0xFFFFFFFFu, val, j);
                    }
                    bool up = ((tid & kk) == 0);
                    bool keepmin = (((tid & j) == 0) == up);
                    val = (keepmin == (val < o)) ? val : o;
                }
            }
            cand[tid] = val;
            __syncthreads();
        } else {
            for (int kk = 2; kk <= CANDCAP; kk <<= 1) {
                for (int j = kk >> 1; j > 0; j >>= 1) {
                    for (int i = tid; i < CANDCAP; i += 1024) {
                        int l = i ^ j;
                        if (l > i) {
                            unsigned long long a = cand[i], c = cand[l];
                            bool up = ((i & kk) == 0);
                            if ((a > c) == up) { cand[i] = c; cand[l] = a; }
                        }
                    }
                    __syncthreads();
                }
            }
        }
        res = cand;
    }

    if (tid < TOPK_) {
        unsigned long long skv = res[tid];
        unsigned idx = (unsigned)(skv & 0xFFFFFFFFu);
        unsigned kb  = ~((unsigned)(skv >> 32));
        float score  = __uint_as_float(kb);
        int m = b * TOPK_ + tid;
        out[m] = (float)b;                                      // ids_batch1
        float4 box = reinterpret_cast<const float4*>(pboxes)[b * N_ + idx];
        reinterpret_cast<float4*>(out + M_)[m] = box;           // p_boxes1
        out[5 * M_ + m] = (float)g_labels[b * N_ + idx];        // p_labels1
        out[6 * M_ + m] = score;                                // p_scores1
        unsigned lm = max(max(mono_bits(box.x), mono_bits(box.y)),
                          max(mono_bits(box.z), mono_bits(box.w)));
        atomicMax(&s_maxb, lm);
    }
    __syncthreads();
    if (tid == 0) atomicMax(&g_maxbits, s_maxb);
}

// ---------------- K3: warp-per-group greedy NMS (exact offset arith) -------
// 640 groups = (label, batch); cross-group IoU is exactly 0 (offset spacing
// >= 2.1 exceeds box extents), so per-group greedy in rank order == jax's
// global greedy.
__global__ void __launch_bounds__(128) k3_nms(float* __restrict__ out) {
    __shared__ float4 kept_s[4][512];
    const int lane = threadIdx.x & 31;
    const int wid  = threadIdx.x >> 5;
    const int g    = blockIdx.x * 4 + wid;      // 0..639
    const int bb   = g & 7;
    const float fc = (float)(g >> 3);
    const unsigned gm = 0xFFFFFFFFu;

    unsigned mb = g_maxbits;
    int ivb = (mb & 0x80000000u) ? (int)(mb & 0x7FFFFFFFu) : ~((int)mb);
    const float mc1 = __fadd_rn(__int_as_float(ivb), 1.0f);
    const float off = __fmul_rn((float)g, mc1);

    float4* kept = kept_s[wid];
    int nk = 0;

    for (int it = 0; it < 16; it++) {
        int r = it * 32 + lane;
        int m = bb * TOPK_ + r;
        bool pred = false;
        if (r < TOPK_) {
            float lab = out[5 * M_ + m];
            float scv = out[6 * M_ + m];
            bool valid = scv > 0.05f;
            pred = valid && (lab == fc);
            if (!valid && fc == 0.0f) out[7 * M_ + m] = 0.0f;  // invalid: keep=0
        }
        unsigned ball = __ballot_sync(gm, pred);
        float4 ob;
        if (pred) {
            float4 bx = reinterpret_cast<float4*>(out + M_)[m];
            ob.x = __fadd_rn(bx.x, off); ob.y = __fadd_rn(bx.y, off);
            ob.z = __fadd_rn(bx.z, off); ob.w = __fadd_rn(bx.w, off);
        }
        while (ball) {
            int src = __ffs(ball) - 1; ball &= ball - 1;
            float4 cb;
            cb.x = __shfl_sync(gm, ob.x, src);
            cb.y = __shfl_sync(gm, ob.y, src);
            cb.z = __shfl_sync(gm, ob.z, src);
            cb.w = __shfl_sync(gm, ob.w, src);
            bool sup = false;
            for (int t = lane; t < nk; t += 32) {
                float4 kb = kept[t];
                float ltx = fmaxf(kb.x, cb.x), lty = fmaxf(kb.y, cb.y);
                float rbx = fminf(kb.z, cb.z), rby = fminf(kb.w, cb.w);
                float wx = fmaxf(__fsub_rn(rbx, ltx), 0.0f);
                float wy = fmaxf(__fsub_rn(rby, lty), 0.0f);
                float inter = __fmul_rn(wx, wy);
                float aa = __fmul_rn(__fsub_rn(kb.z, kb.x), __fsub_rn(kb.w, kb.y));
                float ab = __fmul_rn(__fsub_rn(cb.z, cb.x), __fsub_rn(cb.w, cb.y));
                float un = __fsub_rn(__fadd_rn(aa, ab), inter);
                float iou = __fdiv_rn(inter, fmaxf(un, 1e-9f));
                if (iou > 0.5f) sup = true;
            }
            unsigned sb = __ballot_sync(gm, sup);
            bool keepit = (sb == 0u);
            if (lane == src)
                out[7 * M_ + bb * TOPK_ + it * 32 + src] = keepit ? 1.0f : 0.0f;
            if (keepit) {
                if (lane == 0) kept[nk] = cb;
                nk++;
                __syncwarp(gm);
            }
        }
    }
}

// ---------------- host ----------------
extern "C" void kernel_launch(void* const* d_in, const int* in_sizes, int n_in,
                              void* d_out, int out_size) {
    const float* pconf  = (const float*)d_in[0];
    const float* pboxes = (const float*)d_in[1];
    float* out = (float*)d_out;
    (void)in_sizes; (void)n_in; (void)out_size;

    k1_scores<<<(NANCH * 4 + 255) / 256, 256>>>(pconf);
    k2_topk<<<B_, 1024>>>(pboxes, out);
    k3_nms<<<160, 128>>>(out);
}

// round 16
// speedup vs baseline: 1.1565x; 1.0561x over previous
#include <cuda_runtime.h>
#include <cstdint>

#define B_ 8
#define N_ 40000
#define C_ 80
#define TOPK_ 500
#define M_ (B_ * TOPK_)   // 4000
#define NANCH (B_ * N_)   // 320000
#define NBINS 4096
#define CANDCAP 2048
#define NQ4 (N_ / 4)      // 10000 float4 per batch
#define BLKS_PER_BATCH 625  // k1: 5000 blocks / 8 batches

// Fixed collect threshold: count(score >= T0) ~ 744 +/- 27 per batch for
// sigmoid(max of 80 N(0,1)) scores; exact histogram fallback covers any
// distribution where nsel falls outside [500, 1024].
#define T0_SCORE 0.9707f

// ---------------- scratch (device globals; no allocations) ----------------
__device__ float g_scores[NANCH];
__device__ int   g_labels[NANCH];
__device__ unsigned long long g_cand[B_ * CANDCAP];  // producer-side candidates
__device__ int      g_ccount[B_];        // zero at load; reset by k3 each run
__device__ unsigned g_maxbits;           // monotone-uint max of gathered coords

__device__ __forceinline__ int score_bin(unsigned k) {
    int bin = ((int)(k >> 11)) - (0x3F000000 >> 11);
    return max(0, min(NBINS - 1, bin));
}

// ---------------- XLA-exact sigmoid: 0.5 + 0.5*fast_tanh(0.5x) ------------
__device__ __forceinline__ float jax_sigmoid(float x) {
    float t  = __fmul_rn(0.5f, x);                 // exact
    float at = fabsf(t);
    float tc = fminf(fmaxf(t, -7.99881172180175781f), 7.99881172180175781f);
    float x2 = __fmul_rn(tc, tc);
    float p = -2.76076847742355e-16f;
    p = fmaf(x2, p,  2.00018790482477e-13f);
    p = fmaf(x2, p, -8.60467152213735e-11f);
    p = fmaf(x2, p,  5.12229709037114e-08f);
    p = fmaf(x2, p,  1.48572235717979e-05f);
    p = fmaf(x2, p,  6.37261928875436e-04f);
    p = fmaf(x2, p,  4.89352455891786e-03f);
    p = __fmul_rn(tc, p);
    float q = 1.19825839466702e-06f;
    q = fmaf(x2, q, 1.18534705686654e-04f);
    q = fmaf(x2, q, 2.26843463243900e-03f);
    q = fmaf(x2, q, 4.89352518554385e-03f);
    float r  = __fdiv_rn(p, q);
    float th = (at < 0.0004f) ? t : r;
    return __fadd_rn(0.5f, __fmul_rn(0.5f, th));   // 0.5*th exact -> unambiguous
}

__device__ __forceinline__ unsigned mono_bits(float f) {
    int iv = __float_as_int(f);
    return (iv >= 0) ? ((unsigned)iv | 0x80000000u) : (unsigned)(~iv);
}

// ---------------- K1: per-anchor max/argmax, 4 lanes per anchor ------------
// Each lane owns 20 classes (5 contiguous float4 loaded up front for MLP).
// Streaming top-2 + shfl merge; exact sigmoid re-scan fallback when top-2
// gap < 1e-3 (sigmoid could tie after rounding). min-blocks=6 caps regs at
// 40 (proven no-spill). NEW: candidates (score >= T0) are appended to the
// per-batch global list so k2 never re-scans the 1.25MB score array.
__global__ void __launch_bounds__(256, 6) k1_scores(const float* __restrict__ pconf) {
    if (blockIdx.x == 0 && threadIdx.x == 0) g_maxbits = 0u;   // reset for k2
    int gt = blockIdx.x * 256 + threadIdx.x;
    int a = gt >> 2;
    if (a >= NANCH) return;
    const int sub  = gt & 3;
    const int lane = threadIdx.x & 31;
    const unsigned gm = 0xFu << (lane & ~3);       // 4-lane group mask

    const float4* p = reinterpret_cast<const float4*>(pconf + (size_t)a * C_) + sub * 5;
    float4 v[5];
#pragma unroll
    for (int j = 0; j < 5; j++) v[j] = p[j];

    const int base = sub * 20;
    float m1 = -1e30f, m2 = -1e30f;
    int idx1 = 0;
#pragma unroll
    for (int j = 0; j < 5; j++) {
        float vals[4] = {v[j].x, v[j].y, v[j].z, v[j].w};
#pragma unroll
        for (int q = 0; q < 4; q++) {
            float val = vals[q];
            if (val > m1) { m2 = m1; m1 = val; idx1 = base + j * 4 + q; }
            else          { m2 = fmaxf(m2, val); }
        }
    }
    // merge top-2 across the 4 lanes (exact ties force m2==m1 -> fallback)
#pragma unroll
    for (int d = 1; d < 4; d <<= 1) {
        float om1 = __shfl_xor_sync(gm, m1, d);
        float om2 = __shfl_xor_sync(gm, m2, d);
        int   oi  = __shfl_xor_sync(gm, idx1, d);
        if (om1 > m1 || (om1 == m1 && oi < idx1)) {
            m2 = fmaxf(m1, om2); m1 = om1; idx1 = oi;
        } else {
            m2 = fmaxf(om1, m2);
        }
    }

    float bs; int bl;
    if (m1 - m2 >= 1e-3f) {
        bs = jax_sigmoid(m1);
        bl = idx1;
    } else {
        // exact path (group-uniform branch): reload row (L1-hot) and rescan
        float thr = m1 - 1e-3f;
        bs = -1.0f; bl = 0x7FFFFFFF;
#pragma unroll
        for (int j = 0; j < 5; j++) {
            float4 w = p[j];
            float vals[4] = {w.x, w.y, w.z, w.w};
#pragma unroll
            for (int q = 0; q < 4; q++) {
                if (vals[q] > thr) {
                    float s = jax_sigmoid(vals[q]);
                    if (s > bs) { bs = s; bl = base + j * 4 + q; }  // first idx in-lane
                }
            }
        }
#pragma unroll
        for (int d = 1; d < 4; d <<= 1) {
            float obs = __shfl_xor_sync(gm, bs, d);
            int   obl = __shfl_xor_sync(gm, bl, d);
            if (obs > bs || (obs == bs && obl < bl)) { bs = obs; bl = obl; }
        }
    }
    if (sub == 0) {
        g_scores[a] = bs;
        g_labels[a] = bl;
        if (bs >= T0_SCORE) {
            const int bidx = blockIdx.x / BLKS_PER_BATCH;     // block-uniform
            const unsigned li = (unsigned)(a - bidx * N_);    // index within batch
            int pos = atomicAdd(&g_ccount[bidx], 1);
            if (pos < CANDCAP) {
                unsigned k = __float_as_uint(bs);
                g_cand[bidx * CANDCAP + pos] =
                    ((unsigned long long)(~k) << 32) | li;
            }
        }
    }
}

// ---------------- K2: exact per-batch top-500 (jax.lax.top_k order) --------
// Fast path: candidates come PREBUILT from k1 (no score scan at all);
// bucket sort on the score's high bits ((key-BASE)>>7): 3-barrier warp scan
// of 4096 bins, scatter, per-bucket stable insertion sort (full (~key,idx)
// compare erases append/scatter nondeterminism). Exact histogram-pivot
// fallback scans g_scores for adversarial distributions (cold).
__global__ void __launch_bounds__(1024) k2_topk(const float* __restrict__ pboxes,
                                                float* __restrict__ out) {
    // smem union: cand 16K | hist 16K | sorted 8K (fast) / sA+sB (fallback) | wsum
    __shared__ __align__(16) unsigned char sraw[16384 + 16384 + 8192 + 256];
    unsigned long long* cand   = (unsigned long long*)sraw;             // 2048
    unsigned*           hist   = (unsigned*)(sraw + 16384);             // 4096
    unsigned long long* sorted = (unsigned long long*)(sraw + 32768);   // 1024
    unsigned*           sA     = (unsigned*)(sraw + 32768);             // 1024 (fallback)
    unsigned*           sB     = (unsigned*)(sraw + 32768 + 4096);      // 1024 (fallback)
    unsigned*           wsum   = (unsigned*)(sraw + 32768 + 8192);      // 32
    __shared__ int s_pivot, s_nsel, s_tstar;
    __shared__ unsigned s_maxb;

    const int b = blockIdx.x;
    const int tid = threadIdx.x;
    const int lane = tid & 31;
    const int wid  = tid >> 5;
    const unsigned BASE = __float_as_uint(T0_SCORE);
    const float4* sc4 = reinterpret_cast<const float4*>(g_scores + b * N_);

    if (tid == 0) s_maxb = 0u;
#pragma unroll
    for (int i = 0; i < 4; i++) hist[tid * 4 + i] = 0u;
    __syncthreads();

    const int nsel = g_ccount[b];
    const bool fast = (nsel >= TOPK_ && nsel <= 1024);
    const unsigned long long* res;

    unsigned long long myv = 0;
    unsigned myrb = 0;
    if (fast && tid < nsel) {
        myv = g_cand[b * CANDCAP + tid];
        unsigned k = ~((unsigned)(myv >> 32));
        myrb = 4095u - min(4095u, (k - BASE) >> 7);
        atomicAdd(&hist[myrb], 1u);
    }
    __syncthreads();

    if (fast) {
        // ============ fast path: bucket sort (6 barriers total) ============
        // exclusive scan of hist[0..4095] (ascending rbin = descending score)
        unsigned h0 = hist[tid * 4], h1 = hist[tid * 4 + 1];
        unsigned h2 = hist[tid * 4 + 2], h3 = hist[tid * 4 + 3];
        unsigned s = h0 + h1 + h2 + h3;
        unsigned inc = s;
#pragma unroll
        for (int d = 1; d < 32; d <<= 1) {
            unsigned n = __shfl_up_sync(0xFFFFFFFFu, inc, d);
            if (lane >= d) inc += n;
        }
        if (lane == 31) wsum[wid] = inc;
        __syncthreads();
        if (wid == 0) {
            unsigned v = wsum[lane];
            unsigned i2 = v;
#pragma unroll
            for (int d = 1; d < 32; d <<= 1) {
                unsigned n = __shfl_up_sync(0xFFFFFFFFu, i2, d);
                if (lane >= d) i2 += n;
            }
            wsum[lane] = i2 - v;          // exclusive warp offsets
        }
        __syncthreads();
        unsigned base0 = wsum[wid] + (inc - s);
        hist[tid * 4]     = base0;
        hist[tid * 4 + 1] = base0 + h0;
        hist[tid * 4 + 2] = base0 + h0 + h1;
        hist[tid * 4 + 3] = base0 + h0 + h1 + h2;
        __syncthreads();

        // scatter (hist: start -> end in place)
        if (tid < nsel) {
            unsigned pos = atomicAdd(&hist[myrb], 1u);
            sorted[pos] = myv;
        }
        __syncthreads();

        // per-bucket stable insertion sort (full (~key,idx) compare)
        for (int r = tid; r < 4096; r += 1024) {
            int st = r ? (int)hist[r - 1] : 0;
            int en = (int)hist[r];
            for (int i2 = st + 1; i2 < en; i2++) {
                unsigned long long v = sorted[i2];
                int jx = i2;
                while (jx > st && sorted[jx - 1] > v) {
                    sorted[jx] = sorted[jx - 1]; jx--;
                }
                sorted[jx] = v;
            }
        }
        __syncthreads();
        res = sorted;
    } else {
        // ========== exact fallback: histogram pivot + bitonic sort ==========
        for (int i = tid; i < NBINS; i += 1024) hist[i] = 0u;
        for (int i = tid; i < CANDCAP; i += 1024) cand[i] = ~0ULL;
        if (tid == 0) s_nsel = 0;
        __syncthreads();
#pragma unroll
        for (int j = 0; j < 10; j++) {
            int i4 = j * 1024 + tid;
            if (i4 < NQ4) {
                float4 v = sc4[i4];
                float vals[4] = {v.x, v.y, v.z, v.w};
#pragma unroll
                for (int q = 0; q < 4; q++)
                    atomicAdd(&hist[score_bin(__float_as_uint(vals[q]))], 1u);
            }
        }
        __syncthreads();
        unsigned s = hist[tid * 4] + hist[tid * 4 + 1] + hist[tid * 4 + 2] + hist[tid * 4 + 3];
        sA[tid] = s;
        __syncthreads();
        unsigned* src = sA; unsigned* dst = sB;
        for (int d = 1; d < 1024; d <<= 1) {
            unsigned vv = src[tid] + ((tid + d < 1024) ? src[tid + d] : 0u);
            dst[tid] = vv;
            __syncthreads();
            unsigned* t2 = src; src = dst; dst = t2;
        }
        unsigned* S = src;
        if (S[tid] >= TOPK_ && (tid == 1023 || S[tid + 1] < TOPK_)) s_tstar = tid;
        __syncthreads();
        if (tid == 0) {
            int t = s_tstar;
            unsigned cum = (t == 1023) ? 0u : S[t + 1];
            int P = t * 4;
            for (int bin = t * 4 + 3; bin >= t * 4; bin--) {
                cum += hist[bin];
                if (cum >= TOPK_) { P = bin; break; }
            }
            s_pivot = P;
        }
        __syncthreads();
        const int P = s_pivot;
#pragma unroll
        for (int j = 0; j < 10; j++) {
            int i4 = j * 1024 + tid;
            if (i4 < NQ4) {
                float4 v = sc4[i4];
                float vals[4] = {v.x, v.y, v.z, v.w};
#pragma unroll
                for (int q = 0; q < 4; q++) {
                    unsigned k = __float_as_uint(vals[q]);
                    if (score_bin(k) >= P) {
                        int pos = atomicAdd(&s_nsel, 1);
                        if (pos < CANDCAP)
                            cand[pos] = ((unsigned long long)(~k) << 32)
                                      | (unsigned)(i4 * 4 + q);
                    }
                }
            }
        }
        __syncthreads();
        const int SZ = (s_nsel <= 1024) ? 1024 : CANDCAP;
        if (SZ == 1024) {
            unsigned long long val = cand[tid];
            __syncthreads();
#pragma unroll
            for (int kk = 2; kk <= 1024; kk <<= 1) {
                for (int j = kk >> 1; j > 0; j >>= 1) {
                    unsigned long long o;
                    if (j >= 32) {
                        cand[tid] = val;
                        __syncthreads();
                        o = cand[tid ^ j];
                        __syncthreads();
                    } else {
                        o = __shfl_xor_sync(0xFFFFFFFFu, val, j);
                    }
                    bool up = ((tid & kk) == 0);
                    bool keepmin = (((tid & j) == 0) == up);
                    val = (keepmin == (val < o)) ? val : o;
                }
            }
            cand[tid] = val;
            __syncthreads();
        } else {
            for (int kk = 2; kk <= CANDCAP; kk <<= 1) {
                for (int j = kk >> 1; j > 0; j >>= 1) {
                    for (int i = tid; i < CANDCAP; i += 1024) {
                        int l = i ^ j;
                        if (l > i) {
                            unsigned long long a = cand[i], c = cand[l];
                            bool up = ((i & kk) == 0);
                            if ((a > c) == up) { cand[i] = c; cand[l] = a; }
                        }
                    }
                    __syncthreads();
                }
            }
        }
        res = cand;
    }

    if (tid < TOPK_) {
        unsigned long long skv = res[tid];
        unsigned idx = (unsigned)(skv & 0xFFFFFFFFu);
        unsigned kb  = ~((unsigned)(skv >> 32));
        float score  = __uint_as_float(kb);
        int m = b * TOPK_ + tid;
        out[m] = (float)b;                                      // ids_batch1
        float4 box = reinterpret_cast<const float4*>(pboxes)[b * N_ + idx];
        reinterpret_cast<float4*>(out + M_)[m] = box;           // p_boxes1
        out[5 * M_ + m] = (float)g_labels[b * N_ + idx];        // p_labels1
        out[6 * M_ + m] = score;                                // p_scores1
        unsigned lm = max(max(mono_bits(box.x), mono_bits(box.y)),
                          max(mono_bits(box.z), mono_bits(box.w)));
        atomicMax(&s_maxb, lm);
    }
    __syncthreads();
    if (tid == 0) atomicMax(&g_maxbits, s_maxb);
}

// ---------------- K3: warp-per-group greedy NMS (exact offset arith) -------
// 640 groups = (label, batch); cross-group IoU is exactly 0 (offset spacing
// >= 2.1 exceeds box extents), so per-group greedy in rank order == jax's
// global greedy. Also resets g_ccount for the next graph replay.
__global__ void __launch_bounds__(128) k3_nms(float* __restrict__ out) {
    __shared__ float4 kept_s[4][512];
    const int lane = threadIdx.x & 31;
    const int wid  = threadIdx.x >> 5;
    const int g    = blockIdx.x * 4 + wid;      // 0..639
    const int bb   = g & 7;
    const float fc = (float)(g >> 3);
    const unsigned gm = 0xFFFFFFFFu;

    if (blockIdx.x == 0 && threadIdx.x < B_) g_ccount[threadIdx.x] = 0;

    unsigned mb = g_maxbits;
    int ivb = (mb & 0x80000000u) ? (int)(mb & 0x7FFFFFFFu) : ~((int)mb);
    const float mc1 = __fadd_rn(__int_as_float(ivb), 1.0f);
    const float off = __fmul_rn((float)g, mc1);

    float4* kept = kept_s[wid];
    int nk = 0;

    for (int it = 0; it < 16; it++) {
        int r = it * 32 + lane;
        int m = bb * TOPK_ + r;
        bool pred = false;
        if (r < TOPK_) {
            float lab = out[5 * M_ + m];
            float scv = out[6 * M_ + m];
            bool valid = scv > 0.05f;
            pred = valid && (lab == fc);
            if (!valid && fc == 0.0f) out[7 * M_ + m] = 0.0f;  // invalid: keep=0
        }
        unsigned ball = __ballot_sync(gm, pred);
        float4 ob;
        if (pred) {
            float4 bx = reinterpret_cast<float4*>(out + M_)[m];
            ob.x = __fadd_rn(bx.x, off); ob.y = __fadd_rn(bx.y, off);
            ob.z = __fadd_rn(bx.z, off); ob.w = __fadd_rn(bx.w, off);
        }
        while (ball) {
            int src = __ffs(ball) - 1; ball &= ball - 1;
            float4 cb;
            cb.x = __shfl_sync(gm, ob.x, src);
            cb.y = __shfl_sync(gm, ob.y, src);
            cb.z = __shfl_sync(gm, ob.z, src);
            cb.w = __shfl_sync(gm, ob.w, src);
            bool sup = false;
            for (int t = lane; t < nk; t += 32) {
                float4 kb = kept[t];
                float ltx = fmaxf(kb.x, cb.x), lty = fmaxf(kb.y, cb.y);
                float rbx = fminf(kb.z, cb.z), rby = fminf(kb.w, cb.w);
                float wx = fmaxf(__fsub_rn(rbx, ltx), 0.0f);
                float wy = fmaxf(__fsub_rn(rby, lty), 0.0f);
                float inter = __fmul_rn(wx, wy);
                float aa = __fmul_rn(__fsub_rn(kb.z, kb.x), __fsub_rn(kb.w, kb.y));
                float ab = __fmul_rn(__fsub_rn(cb.z, cb.x), __fsub_rn(cb.w, cb.y));
                float un = __fsub_rn(__fadd_rn(aa, ab), inter);
                float iou = __fdiv_rn(inter, fmaxf(un, 1e-9f));
                if (iou > 0.5f) sup = true;
            }
            unsigned sb = __ballot_sync(gm, sup);
            bool keepit = (sb == 0u);
            if (lane == src)
                out[7 * M_ + bb * TOPK_ + it * 32 + src] = keepit ? 1.0f : 0.0f;
            if (keepit) {
                if (lane == 0) kept[nk] = cb;
                nk++;
                __syncwarp(gm);
            }
        }
    }
}

// ---------------- host ----------------
extern "C" void kernel_launch(void* const* d_in, const int* in_sizes, int n_in,
                              void* d_out, int out_size) {
    const float* pconf  = (const float*)d_in[0];
    const float* pboxes = (const float*)d_in[1];
    float* out = (float*)d_out;
    (void)in_sizes; (void)n_in; (void)out_size;

    k1_scores<<<(NANCH * 4 + 255) / 256, 256>>>(pconf);
    k2_topk<<<B_, 1024>>>(pboxes, out);
    k3_nms<<<160, 128>>>(out);
}